// round 3
// baseline (speedup 1.0000x reference)
#include <cuda_runtime.h>
#include <stdint.h>

// ---------------------------------------------------------------------------
// BalancedCELoss — exact replication of
//   scores = jax.random.uniform(jax.random.key(42), (B, N))
// under jax_threefry_partitionable=True (modern JAX default):
//   per flat element i: (o0, o1) = threefry2x32_20(key=(0,42), counter=(0, i))
//   bits = o0 ^ o1 ;  float = bitcast((bits >> 9) | 0x3f800000) - 1
// Ordering of uniforms == ordering of the 23-bit field (bits >> 9).
// Then per-row top-k (stable: score desc, index asc) of pos/neg CE, mean.
// ---------------------------------------------------------------------------

#define BB   128
#define NN   131072
#define CAP  4096              // candidate slots per (row, class); mean ~1024
#define THRESH 8257536u        // 2^23 - 2^17  -> keep top 1/64 of scores
#define KMAX 64

__device__ unsigned long long g_cand[BB][2][CAP];
__device__ int   g_ccnt[BB][2];
__device__ int   g_cpos[BB];
__device__ float g_loss[BB][2];

// ---------------- threefry2x32-20 with key (0, 42) ----------------
__device__ __forceinline__ uint32_t rotl32(uint32_t x, int d) {
    return __funnelshift_l(x, x, d);
}

__device__ __forceinline__ uint32_t threefry_0_42_xor(uint32_t c0, uint32_t c1) {
    const uint32_t ks0 = 0u;
    const uint32_t ks1 = 42u;
    const uint32_t ks2 = 0x1BD11BDAu ^ ks0 ^ ks1;   // 0x1BD11BF0
    uint32_t x0 = c0 + ks0;
    uint32_t x1 = c1 + ks1;
#define TF_MIX(r) { x0 += x1; x1 = rotl32(x1, (r)); x1 ^= x0; }
    TF_MIX(13) TF_MIX(15) TF_MIX(26) TF_MIX(6)   x0 += ks1; x1 += ks2 + 1u;
    TF_MIX(17) TF_MIX(29) TF_MIX(16) TF_MIX(24)  x0 += ks2; x1 += ks0 + 2u;
    TF_MIX(13) TF_MIX(15) TF_MIX(26) TF_MIX(6)   x0 += ks0; x1 += ks1 + 3u;
    TF_MIX(17) TF_MIX(29) TF_MIX(16) TF_MIX(24)  x0 += ks1; x1 += ks2 + 4u;
    TF_MIX(13) TF_MIX(15) TF_MIX(26) TF_MIX(6)   x0 += ks2; x1 += ks0 + 5u;
#undef TF_MIX
    return x0 ^ x1;
}

// ---------------- kernel 0: zero the per-launch counters ----------------
__global__ void init_kernel() {
    int i = threadIdx.x;
    if (i < BB) {
        g_cpos[i]    = 0;
        g_ccnt[i][0] = 0;
        g_ccnt[i][1] = 0;
    }
}

// ---------------- kernel 1: scores + count_pos + candidate filter ----------
__global__ void score_kernel(const int* __restrict__ target) {
    const int n = blockIdx.x * blockDim.x + threadIdx.x;   // column 0..N-1
    const int b = blockIdx.y;                              // row 0..127
    const int tid  = threadIdx.x;
    const int lane = tid & 31;

    __shared__ int s_pos;
    if (tid == 0) s_pos = 0;
    __syncthreads();

    const uint32_t i = (uint32_t)b * (uint32_t)NN + (uint32_t)n;  // < 2^24
    // partitionable counter-mode: counter = (hi, lo) = (0, i); bits = o0 ^ o1
    uint32_t s = threefry_0_42_xor(0u, i) >> 9;       // 23-bit score field

    int t = target[(size_t)b * NN + n];

    // per-block count_pos aggregation
    unsigned m = __ballot_sync(0xffffffffu, t == 1);
    if (lane == 0) atomicAdd(&s_pos, __popc(m));

    // candidate filter: key = (score << 17) | (N-1-n)  (max key => max score, min n)
    if (s >= THRESH) {
        int cls = (t == 1) ? 0 : 1;
        int p = atomicAdd(&g_ccnt[b][cls], 1);
        if (p < CAP)
            g_cand[b][cls][p] =
                ((unsigned long long)s << 17) | (unsigned)(NN - 1 - n);
    }

    __syncthreads();
    if (tid == 0) atomicAdd(&g_cpos[b], s_pos);
}

// ---------------- kernel 2: per-(row, class) top-k + CE ----------------
__device__ __forceinline__ void warp_argmax(unsigned long long& v, int& i) {
#pragma unroll
    for (int o = 16; o > 0; o >>= 1) {
        unsigned long long vo = __shfl_down_sync(0xffffffffu, v, o);
        int io = __shfl_down_sync(0xffffffffu, i, o);
        if (vo > v) { v = vo; i = io; }
    }
}

__global__ void select_kernel(const float* __restrict__ logits,
                              const int* __restrict__ np_ptr,
                              const int* __restrict__ nn_ptr) {
    const int b   = blockIdx.x >> 1;
    const int cls = blockIdx.x & 1;          // 0 = pos (target==1), 1 = neg
    const int tid = threadIdx.x;

    const int num_pos = np_ptr ? np_ptr[0] : 16;
    const int num_neg = nn_ptr ? nn_ptr[0] : 48;

    int k = (cls == 0) ? num_pos : num_neg;
    if (k > KMAX) k = KMAX;
    if (k < 0)    k = 0;

    int cnt  = min(g_ccnt[b][cls], CAP);
    int cpos = g_cpos[b];

    long long mn;
    if (cls == 0) {
        mn = min((long long)cpos, (long long)num_pos);
    } else {
        long long q = ((long long)cpos * (long long)num_neg) /
                      (long long)(num_pos > 0 ? num_pos : 1);
        mn = min(q, (long long)num_neg);
    }
    int min_k = (int)mn;

    __shared__ unsigned long long keys[CAP];
    __shared__ unsigned long long wk[8];
    __shared__ int wi[8];
    __shared__ unsigned int seln[KMAX];
    __shared__ float fsum[256];

    for (int i = tid; i < cnt; i += 256) keys[i] = g_cand[b][cls][i];
    __syncthreads();

    const int ksel = min(k, cnt);
    const int lane = tid & 31;
    const int wid  = tid >> 5;

    for (int j = 0; j < ksel; j++) {
        unsigned long long best = 0ULL;
        int bi = -1;
        for (int i = tid; i < cnt; i += 256) {
            unsigned long long v = keys[i];
            if (v > best) { best = v; bi = i; }
        }
        warp_argmax(best, bi);
        if (lane == 0) { wk[wid] = best; wi[wid] = bi; }
        __syncthreads();
        if (wid == 0) {
            unsigned long long v = (lane < 8) ? wk[lane] : 0ULL;
            int i = (lane < 8) ? wi[lane] : -1;
            warp_argmax(v, i);
            if (lane == 0) {
                seln[j] = (unsigned)(NN - 1 - (unsigned)(v & 0x1FFFFu));
                if (i >= 0) keys[i] = 0ULL;   // remove winner
            }
        }
        __syncthreads();
    }

    // CE at selected indices (first min_k are valid)
    float v = 0.0f;
    if (tid < ksel && tid < min_k) {
        unsigned n = seln[tid];
        const float* p = logits + (((size_t)b * NN) + n) * 2;
        float l0 = p[0], l1 = p[1];
        float m  = fmaxf(l0, l1);
        float lse = m + logf(expf(l0 - m) + expf(l1 - m));
        float lt  = (cls == 0) ? l1 : l0;   // pos rows target 1, neg target 0
        v = lse - lt;
    }
    fsum[tid] = v;
    __syncthreads();
#pragma unroll
    for (int s = 128; s > 0; s >>= 1) {
        if (tid < s) fsum[tid] += fsum[tid + s];
        __syncthreads();
    }
    if (tid == 0) g_loss[b][cls] = fsum[0] / (float)max(min_k, 1);
}

// ---------------- kernel 3: deterministic final mean ----------------
__global__ void finalize_kernel(float* __restrict__ out) {
    __shared__ float fs[BB];
    int b = threadIdx.x;
    fs[b] = (g_loss[b][0] + g_loss[b][1]) * 0.5f;
    __syncthreads();
#pragma unroll
    for (int s = 64; s > 0; s >>= 1) {
        if (b < s) fs[b] += fs[b + s];
        __syncthreads();
    }
    if (b == 0) out[0] = fs[0] / (float)BB;
}

// ---------------------------------------------------------------------------
extern "C" void kernel_launch(void* const* d_in, const int* in_sizes, int n_in,
                              void* d_out, int out_size) {
    const float* logits = (const float*)d_in[0];
    const int*   target = (const int*)d_in[1];
    const int*   np_ptr = (n_in > 2) ? (const int*)d_in[2] : nullptr;
    const int*   nn_ptr = (n_in > 3) ? (const int*)d_in[3] : nullptr;

    init_kernel<<<1, 128>>>();
    dim3 grid(NN / 256, BB);
    score_kernel<<<grid, 256>>>(target);
    select_kernel<<<BB * 2, 256>>>(logits, np_ptr, nn_ptr);
    finalize_kernel<<<1, BB>>>((float*)d_out);
}